// round 1
// baseline (speedup 1.0000x reference)
#include <cuda_runtime.h>
#include <math.h>

#define L_TOT 1568
#define T_LEN 784
#define D_MODEL 768
#define N_HEADS 12
#define DIM_HEAD 64
#define D_FF 3072
#define BATCH 4
#define ROWS (BATCH * L_TOT)          // 6272
#define NPATCH 196

// ---------------- scratch (device globals; no allocation allowed) ----------------
__device__ float g_xaug[ROWS * D_MODEL];                 // residual stream (post ln1)
__device__ float g_h[ROWS * D_MODEL];                    // ln_att output
__device__ float g_qkv[ROWS * 3 * D_MODEL];              // [row][2304]
__device__ float g_dots[48u * L_TOT * L_TOT];            // [b*12+h][i][j]  (~472MB)
__device__ float g_ctx[ROWS * D_MODEL];                  // attention context
__device__ float g_y2[ROWS * D_MODEL];                   // ln2 output
__device__ float g_ff[ROWS * D_FF];                      // ff hidden

// ---------------- helpers ----------------
__device__ __forceinline__ void block_reduce2(float& a, float& b, float* s1, float* s2) {
    int tid = threadIdx.x;
    s1[tid] = a; s2[tid] = b; __syncthreads();
    #pragma unroll
    for (int s = 128; s; s >>= 1) {
        if (tid < s) { s1[tid] += s1[tid + s]; s2[tid] += s2[tid + s]; }
        __syncthreads();
    }
    a = s1[0]; b = s2[0]; __syncthreads();
}

// Build x_aug = ln1(concat(mem[:, :T], x)), then h = ln_att(x_aug).
// One block per row, 256 threads, 3 elements per thread (768 = 256*3).
__global__ void ln_build_kernel(const float* __restrict__ x,
                                const float* __restrict__ mem,
                                const float* __restrict__ g1, const float* __restrict__ b1,
                                const float* __restrict__ ga, const float* __restrict__ ba) {
    __shared__ float s1[256], s2[256];
    int row = blockIdx.x;
    int b = row / L_TOT;
    int l = row - b * L_TOT;
    const float* src = (l < T_LEN)
        ? mem + ((long long)b * 1024 + l) * D_MODEL
        : x   + ((long long)b * T_LEN + (l - T_LEN)) * D_MODEL;
    int tid = threadIdx.x;
    float v[3]; float sum = 0.f, sq = 0.f;
    #pragma unroll
    for (int i = 0; i < 3; i++) {
        v[i] = src[tid + 256 * i];
        sum += v[i]; sq += v[i] * v[i];
    }
    block_reduce2(sum, sq, s1, s2);
    float mu = sum * (1.f / 768.f);
    float var = sq * (1.f / 768.f) - mu * mu;
    float rstd = rsqrtf(var + 1e-5f);

    float w[3]; sum = 0.f; sq = 0.f;
    #pragma unroll
    for (int i = 0; i < 3; i++) {
        int idx = tid + 256 * i;
        w[i] = (v[i] - mu) * rstd * g1[idx] + b1[idx];
        g_xaug[(long long)row * D_MODEL + idx] = w[i];
        sum += w[i]; sq += w[i] * w[i];
    }
    block_reduce2(sum, sq, s1, s2);
    float mu2 = sum * (1.f / 768.f);
    float var2 = sq * (1.f / 768.f) - mu2 * mu2;
    float rstd2 = rsqrtf(var2 + 1e-5f);
    #pragma unroll
    for (int i = 0; i < 3; i++) {
        int idx = tid + 256 * i;
        g_h[(long long)row * D_MODEL + idx] = (w[i] - mu2) * rstd2 * ga[idx] + ba[idx];
    }
}

// Plain layernorm: dst = ln(src) with g,b. One block per row.
__global__ void ln_kernel(const float* __restrict__ src, float* __restrict__ dst,
                          const float* __restrict__ g, const float* __restrict__ b) {
    __shared__ float s1[256], s2[256];
    int row = blockIdx.x;
    int tid = threadIdx.x;
    const float* p = src + (long long)row * D_MODEL;
    float v[3]; float sum = 0.f, sq = 0.f;
    #pragma unroll
    for (int i = 0; i < 3; i++) {
        v[i] = p[tid + 256 * i];
        sum += v[i]; sq += v[i] * v[i];
    }
    block_reduce2(sum, sq, s1, s2);
    float mu = sum * (1.f / 768.f);
    float var = sq * (1.f / 768.f) - mu * mu;
    float rstd = rsqrtf(var + 1e-5f);
    #pragma unroll
    for (int i = 0; i < 3; i++) {
        int idx = tid + 256 * i;
        dst[(long long)row * D_MODEL + idx] = (v[i] - mu) * rstd * g[idx] + b[idx];
    }
}

// Generic fp32 tiled GEMM:
//   BT=true : C[m,n] = scale * sum_k A[m*lda+k] * B[n*ldb+k]   (B row-major [N,K])
//   BT=false: C[m,n] = scale * sum_k A[m*lda+k] * B[k*ldb+n]   (B row-major [K,N])
// Epilogue: +bias[n], silu, +res[m*ldc+n]. Batched via (b,h) offsets (blockIdx.z = b*H+h).
// Requirements: K % 16 == 0, A/B element offsets 4-aligned at k0 multiples of 16.
template <bool BT, bool BIAS, bool RES, bool SILU>
__global__ void gemm_kernel(const float* __restrict__ A, const float* __restrict__ B,
                            float* C, const float* bias, const float* res,
                            int M, int N, int K, int lda, int ldb, int ldc,
                            long long Ab, long long Ah, long long Bb, long long Bh,
                            long long Cb, long long Ch, int H, float scale) {
    __shared__ float As[16][64];
    __shared__ float Bs[16][64];
    int tid = threadIdx.x;
    int bz = blockIdx.z;
    int b = bz / H, h = bz - b * H;
    A += b * Ab + h * Ah;
    B += b * Bb + h * Bh;
    C += b * Cb + h * Ch;
    if (RES) res += b * Cb + h * Ch;

    int m0 = blockIdx.y * 64, n0 = blockIdx.x * 64;
    int tx = tid & 15, ty = tid >> 4;
    int arow = tid >> 2;
    int akc = (tid & 3) << 2;

    float acc[4][4] = {};

    for (int k0 = 0; k0 < K; k0 += 16) {
        {
            int m = m0 + arow;
            float4 v = make_float4(0.f, 0.f, 0.f, 0.f);
            if (m < M) v = *(const float4*)(A + (long long)m * lda + k0 + akc);
            As[akc + 0][arow] = v.x; As[akc + 1][arow] = v.y;
            As[akc + 2][arow] = v.z; As[akc + 3][arow] = v.w;
        }
        if (BT) {
            int n = n0 + arow;
            float4 v = make_float4(0.f, 0.f, 0.f, 0.f);
            if (n < N) v = *(const float4*)(B + (long long)n * ldb + k0 + akc);
            Bs[akc + 0][arow] = v.x; Bs[akc + 1][arow] = v.y;
            Bs[akc + 2][arow] = v.z; Bs[akc + 3][arow] = v.w;
        } else {
            int kr = tid >> 4;
            int nc = (tid & 15) << 2;
            int n = n0 + nc;
            const float* Bp = B + (long long)(k0 + kr) * ldb + n;
            float4 v = make_float4(0.f, 0.f, 0.f, 0.f);
            if (n + 3 < N) v = *(const float4*)Bp;
            else {
                if (n + 0 < N) v.x = Bp[0];
                if (n + 1 < N) v.y = Bp[1];
                if (n + 2 < N) v.z = Bp[2];
                if (n + 3 < N) v.w = Bp[3];
            }
            Bs[kr][nc + 0] = v.x; Bs[kr][nc + 1] = v.y;
            Bs[kr][nc + 2] = v.z; Bs[kr][nc + 3] = v.w;
        }
        __syncthreads();
        #pragma unroll
        for (int kk = 0; kk < 16; kk++) {
            float4 a4 = *(const float4*)&As[kk][ty << 2];
            float4 b4 = *(const float4*)&Bs[kk][tx << 2];
            float av[4] = {a4.x, a4.y, a4.z, a4.w};
            float bv[4] = {b4.x, b4.y, b4.z, b4.w};
            #pragma unroll
            for (int i = 0; i < 4; i++)
                #pragma unroll
                for (int j = 0; j < 4; j++)
                    acc[i][j] += av[i] * bv[j];
        }
        __syncthreads();
    }

    #pragma unroll
    for (int i = 0; i < 4; i++) {
        int m = m0 + (ty << 2) + i;
        if (m >= M) continue;
        #pragma unroll
        for (int j = 0; j < 4; j++) {
            int n = n0 + (tx << 2) + j;
            if (n >= N) continue;
            float v = acc[i][j] * scale;
            if (BIAS) v += bias[n];
            if (SILU) v = v / (1.f + expf(-v));
            if (RES) v += res[(long long)m * ldc + n];
            C[(long long)m * ldc + n] = v;
        }
    }
}

// Masked softmax over scores; mask is analytic:
//   query row r attends keys [0, kmax), kmax = (r<784) ? 1568 : (r/196 + 1)*196.
// Masked tail is zeroed so the PV GEMM can run full-K.
__global__ void softmax_kernel() {
    __shared__ float sb[256];
    int r = blockIdx.x;
    int z = blockIdx.y;
    float* p = g_dots + (long long)z * L_TOT * L_TOT + (long long)r * L_TOT;
    int kmax = (r < T_LEN) ? L_TOT : ((r / NPATCH) + 1) * NPATCH;
    int tid = threadIdx.x;

    float m = -1e30f;
    for (int j = tid; j < kmax; j += 256) m = fmaxf(m, p[j]);
    sb[tid] = m; __syncthreads();
    #pragma unroll
    for (int s = 128; s; s >>= 1) {
        if (tid < s) sb[tid] = fmaxf(sb[tid], sb[tid + s]);
        __syncthreads();
    }
    m = sb[0]; __syncthreads();

    float sum = 0.f;
    for (int j = tid; j < kmax; j += 256) sum += expf(p[j] - m);
    sb[tid] = sum; __syncthreads();
    #pragma unroll
    for (int s = 128; s; s >>= 1) {
        if (tid < s) sb[tid] += sb[tid + s];
        __syncthreads();
    }
    float inv = 1.f / sb[0];
    __syncthreads();

    for (int j = tid; j < kmax; j += 256) p[j] = expf(p[j] - m) * inv;
    for (int j = kmax + tid; j < L_TOT; j += 256) p[j] = 0.f;
}

// out[b, t, d] = xaug[b*L + 784 + t, d]
__global__ void extract_kernel(float* __restrict__ out) {
    long long i = (long long)blockIdx.x * 256 + threadIdx.x;
    const long long TOT = (long long)BATCH * T_LEN * D_MODEL;
    if (i >= TOT) return;
    long long d = i % D_MODEL;
    long long t = (i / D_MODEL) % T_LEN;
    long long b = i / ((long long)D_MODEL * T_LEN);
    out[i] = g_xaug[((long long)b * L_TOT + T_LEN + t) * D_MODEL + d];
}

// ---------------- launch ----------------
extern "C" void kernel_launch(void* const* d_in, const int* in_sizes, int n_in,
                              void* d_out, int out_size) {
    const float* x        = (const float*)d_in[0];
    const float* memory   = (const float*)d_in[1];
    const float* ln_att_g = (const float*)d_in[2];
    const float* ln_att_b = (const float*)d_in[3];
    const float* w_qkv    = (const float*)d_in[4];
    const float* w_out    = (const float*)d_in[5];
    const float* b_out    = (const float*)d_in[6];
    const float* ln1_g    = (const float*)d_in[7];
    const float* ln1_b    = (const float*)d_in[8];
    const float* ln2_g    = (const float*)d_in[9];
    const float* ln2_b    = (const float*)d_in[10];
    const float* w1       = (const float*)d_in[11];
    const float* b1       = (const float*)d_in[12];
    const float* w2       = (const float*)d_in[13];
    const float* b2       = (const float*)d_in[14];
    float* out = (float*)d_out;

    float *xaug, *h, *qkv, *dots, *ctx, *y2, *ff;
    cudaGetSymbolAddress((void**)&xaug, g_xaug);
    cudaGetSymbolAddress((void**)&h,    g_h);
    cudaGetSymbolAddress((void**)&qkv,  g_qkv);
    cudaGetSymbolAddress((void**)&dots, g_dots);
    cudaGetSymbolAddress((void**)&ctx,  g_ctx);
    cudaGetSymbolAddress((void**)&y2,   g_y2);
    cudaGetSymbolAddress((void**)&ff,   g_ff);

    // 1) x_aug = ln1(concat(mem, x)); h = ln_att(x_aug)
    ln_build_kernel<<<ROWS, 256>>>(x, memory, ln1_g, ln1_b, ln_att_g, ln_att_b);

    // 2) qkv = h @ w_qkv^T   [6272, 2304]
    gemm_kernel<true, false, false, false><<<dim3(36, 98, 1), 256>>>(
        h, w_qkv, qkv, nullptr, nullptr,
        ROWS, 3 * D_MODEL, D_MODEL, D_MODEL, D_MODEL, 3 * D_MODEL,
        0, 0, 0, 0, 0, 0, 1, 1.f);

    // 3) dots[b,h] = Q @ K^T * scale   [1568,1568] per (b,h)
    gemm_kernel<true, false, false, false><<<dim3(25, 25, 48), 256>>>(
        qkv, qkv + D_MODEL, dots, nullptr, nullptr,
        L_TOT, L_TOT, DIM_HEAD, 3 * D_MODEL, 3 * D_MODEL, L_TOT,
        (long long)L_TOT * 3 * D_MODEL, DIM_HEAD,
        (long long)L_TOT * 3 * D_MODEL, DIM_HEAD,
        (long long)N_HEADS * L_TOT * L_TOT, (long long)L_TOT * L_TOT,
        N_HEADS, 0.125f);

    // 4) masked softmax (in place, zeros masked tail)
    softmax_kernel<<<dim3(L_TOT, 48), 256>>>();

    // 5) ctx[b,h] = P @ V   [1568,64] per (b,h), written interleaved to [row][768]
    gemm_kernel<false, false, false, false><<<dim3(1, 25, 48), 256>>>(
        dots, qkv + 2 * D_MODEL, ctx, nullptr, nullptr,
        L_TOT, DIM_HEAD, L_TOT, L_TOT, 3 * D_MODEL, D_MODEL,
        (long long)N_HEADS * L_TOT * L_TOT, (long long)L_TOT * L_TOT,
        (long long)L_TOT * 3 * D_MODEL, DIM_HEAD,
        (long long)L_TOT * D_MODEL, DIM_HEAD,
        N_HEADS, 1.f);

    // 6) xaug += ctx @ w_out^T + b_out
    gemm_kernel<true, true, true, false><<<dim3(12, 98, 1), 256>>>(
        ctx, w_out, xaug, b_out, xaug,
        ROWS, D_MODEL, D_MODEL, D_MODEL, D_MODEL, D_MODEL,
        0, 0, 0, 0, 0, 0, 1, 1.f);

    // 7) y2 = ln2(xaug)
    ln_kernel<<<ROWS, 256>>>(xaug, y2, ln2_g, ln2_b);

    // 8) ff = silu(y2 @ w1^T + b1)   [6272, 3072]
    gemm_kernel<true, true, false, true><<<dim3(48, 98, 1), 256>>>(
        y2, w1, ff, b1, nullptr,
        ROWS, D_FF, D_MODEL, D_MODEL, D_MODEL, D_FF,
        0, 0, 0, 0, 0, 0, 1, 1.f);

    // 9) xaug += ff @ w2^T + b2
    gemm_kernel<true, true, true, false><<<dim3(12, 98, 1), 256>>>(
        ff, w2, xaug, b2, xaug,
        ROWS, D_MODEL, D_FF, D_FF, D_FF, D_MODEL,
        0, 0, 0, 0, 0, 0, 1, 1.f);

    // 10) extract last T rows
    long long tot = (long long)BATCH * T_LEN * D_MODEL;
    extract_kernel<<<(unsigned)((tot + 255) / 256), 256>>>(out);
}

// round 2
// speedup vs baseline: 2.6238x; 2.6238x over previous
#include <cuda_runtime.h>
#include <math.h>

#define L_TOT 1568
#define T_LEN 784
#define D_MODEL 768
#define N_HEADS 12
#define DIM_HEAD 64
#define D_FF 3072
#define BATCH 4
#define ROWS (BATCH * L_TOT)          // 6272
#define NPATCH 196

// ---------------- scratch ----------------
__device__ float g_xaug[ROWS * D_MODEL];
__device__ float g_h[ROWS * D_MODEL];
__device__ float g_qkv[ROWS * 3 * D_MODEL];
__device__ float g_dots[48u * L_TOT * L_TOT];
__device__ float g_ctx[ROWS * D_MODEL];
__device__ float g_y2[ROWS * D_MODEL];
__device__ float g_ff[ROWS * D_FF];

// ---------------- small helpers ----------------
__device__ __forceinline__ unsigned smem_u32(const void* p) {
    unsigned r;
    asm("{ .reg .u64 t; cvta.to.shared.u64 t, %1; cvt.u32.u64 %0, t; }" : "=r"(r) : "l"(p));
    return r;
}
__device__ __forceinline__ void cp16(unsigned dst, const void* src, bool valid) {
    int sz = valid ? 16 : 0;
    asm volatile("cp.async.cg.shared.global [%0], [%1], 16, %2;" :: "r"(dst), "l"(src), "r"(sz));
}
__device__ __forceinline__ unsigned f2tf(float f) {
    unsigned u;
    asm("cvt.rna.tf32.f32 %0, %1;" : "=r"(u) : "f"(f));
    return u;
}
__device__ __forceinline__ void mma_tf32(float4& d, const unsigned a[4], const unsigned b[2]) {
    asm volatile(
        "mma.sync.aligned.m16n8k8.row.col.f32.tf32.tf32.f32 "
        "{%0,%1,%2,%3}, {%4,%5,%6,%7}, {%8,%9}, {%0,%1,%2,%3};"
        : "+f"(d.x), "+f"(d.y), "+f"(d.z), "+f"(d.w)
        : "r"(a[0]), "r"(a[1]), "r"(a[2]), "r"(a[3]), "r"(b[0]), "r"(b[1]));
}

// ---------------- tf32 tensor-core GEMM ----------------
// BT=true : C[m,n] = scale * sum_k A[m,k] * B[n,k]   (B row-major [N,K])
// BT=false: C[m,n] = scale * sum_k A[m,k] * B[k,n]   (B row-major [K,N])
// Epilogue: +bias[n]; silu; +res. Batched via blockIdx.z = b*H + h.
// K % 16 == 0 required. BM=128 fixed.
template <int BN, bool BT, bool BIAS, bool RES, bool SILU>
__global__ void __launch_bounds__(256, 1)
mma_gemm(const float* __restrict__ A, const float* __restrict__ B,
         float* __restrict__ C, const float* __restrict__ bias, const float* __restrict__ res,
         int M, int N, int K, int lda, int ldb, int ldc,
         long long Ab, long long Ah, long long Bb, long long Bh,
         long long Cb, long long Ch, int H, float scale,
         int qk_skip, int pv_limit) {
    const int BM = 128, BK = 16, PAD = 20;
    const int NT = BN / 16;  // n-tiles (8 cols each) per warp (warp n-extent = BN/2)

    __shared__ float As[2][BM * PAD];
    __shared__ float Bs[2][BN * PAD];

    int tid = threadIdx.x;
    int bz = blockIdx.z, b = bz / H, h = bz - b * H;
    A += b * Ab + h * Ah;
    B += b * Bb + h * Bh;
    C += b * Cb + h * Ch;
    const float* resp = RES ? (res + b * Cb + h * Ch) : nullptr;

    int m0 = blockIdx.y * BM, n0 = blockIdx.x * BN;

    int kt = 0;
    if (qk_skip | pv_limit) {
        int last = min(m0 + BM - 1, M - 1);
        kt = (m0 < T_LEN) ? L_TOT : ((last / NPATCH) + 1) * NPATCH;
    }
    if (qk_skip && n0 >= kt) return;
    int Keff = K;
    if (pv_limit) Keff = min(K, (kt + 15) & ~15);

    int warp = tid >> 5, lane = tid & 31;
    int wm = warp & 3, wn = warp >> 2;            // 4 x 2 warp grid
    int mw = m0 + wm * 32;                         // warp m origin (2 mtiles of 16)
    int nw = n0 + wn * (BN / 2);                   // warp n origin (NT ntiles of 8)
    int g = lane >> 2, tg = lane & 3;

    float4 acc[2][NT];
    #pragma unroll
    for (int i = 0; i < 2; i++)
        #pragma unroll
        for (int j = 0; j < NT; j++) acc[i][j] = make_float4(0.f, 0.f, 0.f, 0.f);

    unsigned sA = smem_u32(As), sB = smem_u32(Bs);

    auto load_stage = [&](int ks, int buf) {
        // A tile: 128 x 16 via cp.async (2 float4 chunks / thread)
        #pragma unroll
        for (int i = 0; i < 2; i++) {
            int c = tid + i * 256;
            int m = c >> 2, kc = (c & 3) << 2;
            unsigned dst = sA + (buf * BM * PAD + m * PAD + kc) * 4;
            const float* src = A + (long long)(m0 + m) * lda + ks + kc;
            cp16(dst, src, (m0 + m) < M);
        }
        if (BT) {
            #pragma unroll
            for (int i = 0; i < (BN * 4) / 256; i++) {
                int c = tid + i * 256;
                int n = c >> 2, kc = (c & 3) << 2;
                unsigned dst = sB + (buf * BN * PAD + n * PAD + kc) * 4;
                const float* src = B + (long long)(n0 + n) * ldb + ks + kc;
                cp16(dst, src, (n0 + n) < N);
            }
        } else {
            // B [K,N] -> transpose into Bs[n][k]
            float* bb = &Bs[buf][0];
            for (int c = tid; c < 4 * BN; c += 256) {
                int k = c / (BN / 4);
                int nc = (c % (BN / 4)) * 4;
                float4 v = make_float4(0.f, 0.f, 0.f, 0.f);
                const float* src = B + (long long)(ks + k) * ldb + n0 + nc;
                if (n0 + nc + 3 < N) v = *(const float4*)src;
                else {
                    if (n0 + nc + 0 < N) v.x = src[0];
                    if (n0 + nc + 1 < N) v.y = src[1];
                    if (n0 + nc + 2 < N) v.z = src[2];
                }
                float* bp = bb + nc * PAD + k;
                bp[0] = v.x; bp[PAD] = v.y; bp[2 * PAD] = v.z; bp[3 * PAD] = v.w;
            }
        }
    };

    auto compute = [&](int buf) {
        const float* Ap = &As[0][buf * BM * PAD];
        const float* Bp = &Bs[0][buf * BN * PAD];
        #pragma unroll
        for (int ks = 0; ks < BK; ks += 8) {
            unsigned af[2][4];
            #pragma unroll
            for (int i = 0; i < 2; i++) {
                const float* p = Ap + (wm * 32 + i * 16 + g) * PAD + ks + tg;
                af[i][0] = f2tf(p[0]);
                af[i][1] = f2tf(p[8 * PAD]);
                af[i][2] = f2tf(p[4]);
                af[i][3] = f2tf(p[8 * PAD + 4]);
            }
            unsigned bf[NT][2];
            #pragma unroll
            for (int j = 0; j < NT; j++) {
                const float* p = Bp + (wn * (BN / 2) + j * 8 + g) * PAD + ks + tg;
                bf[j][0] = f2tf(p[0]);
                bf[j][1] = f2tf(p[4]);
            }
            #pragma unroll
            for (int i = 0; i < 2; i++)
                #pragma unroll
                for (int j = 0; j < NT; j++)
                    mma_tf32(acc[i][j], af[i], bf[j]);
        }
    };

    int numK = Keff / BK;
    load_stage(0, 0);
    asm volatile("cp.async.commit_group;");
    for (int it = 0; it < numK; it++) {
        if (it + 1 < numK) {
            load_stage((it + 1) * BK, (it + 1) & 1);
            asm volatile("cp.async.commit_group;");
            asm volatile("cp.async.wait_group 1;");
        } else {
            asm volatile("cp.async.wait_group 0;");
        }
        __syncthreads();
        compute(it & 1);
        __syncthreads();
    }

    // epilogue
    #pragma unroll
    for (int i = 0; i < 2; i++) {
        #pragma unroll
        for (int half = 0; half < 2; half++) {
            int r = mw + i * 16 + g + half * 8;
            if (r >= M) continue;
            long long base = (long long)r * ldc;
            #pragma unroll
            for (int j = 0; j < NT; j++) {
                float v0 = half ? acc[i][j].z : acc[i][j].x;
                float v1 = half ? acc[i][j].w : acc[i][j].y;
                int c0 = nw + j * 8 + tg * 2;
                if (c0 < N) {
                    float v = v0 * scale;
                    if (BIAS) v += bias[c0];
                    if (SILU) v = v / (1.f + expf(-v));
                    if (RES) v += resp[base + c0];
                    C[base + c0] = v;
                }
                if (c0 + 1 < N) {
                    float v = v1 * scale;
                    if (BIAS) v += bias[c0 + 1];
                    if (SILU) v = v / (1.f + expf(-v));
                    if (RES) v += resp[base + c0 + 1];
                    C[base + c0 + 1] = v;
                }
            }
        }
    }
}

// ---------------- layernorms ----------------
__device__ __forceinline__ void block_reduce2(float& a, float& b, float* s1, float* s2) {
    int tid = threadIdx.x;
    s1[tid] = a; s2[tid] = b; __syncthreads();
    #pragma unroll
    for (int s = 128; s; s >>= 1) {
        if (tid < s) { s1[tid] += s1[tid + s]; s2[tid] += s2[tid + s]; }
        __syncthreads();
    }
    a = s1[0]; b = s2[0]; __syncthreads();
}

__global__ void ln_build_kernel(const float* __restrict__ x,
                                const float* __restrict__ mem,
                                const float* __restrict__ g1, const float* __restrict__ b1,
                                const float* __restrict__ ga, const float* __restrict__ ba) {
    __shared__ float s1[256], s2[256];
    int row = blockIdx.x;
    int b = row / L_TOT;
    int l = row - b * L_TOT;
    const float* src = (l < T_LEN)
        ? mem + ((long long)b * 1024 + l) * D_MODEL
        : x   + ((long long)b * T_LEN + (l - T_LEN)) * D_MODEL;
    int tid = threadIdx.x;
    float v[3]; float sum = 0.f, sq = 0.f;
    #pragma unroll
    for (int i = 0; i < 3; i++) {
        v[i] = src[tid + 256 * i];
        sum += v[i]; sq += v[i] * v[i];
    }
    block_reduce2(sum, sq, s1, s2);
    float mu = sum * (1.f / 768.f);
    float var = sq * (1.f / 768.f) - mu * mu;
    float rstd = rsqrtf(var + 1e-5f);

    float w[3]; sum = 0.f; sq = 0.f;
    #pragma unroll
    for (int i = 0; i < 3; i++) {
        int idx = tid + 256 * i;
        w[i] = (v[i] - mu) * rstd * g1[idx] + b1[idx];
        g_xaug[(long long)row * D_MODEL + idx] = w[i];
        sum += w[i]; sq += w[i] * w[i];
    }
    block_reduce2(sum, sq, s1, s2);
    float mu2 = sum * (1.f / 768.f);
    float var2 = sq * (1.f / 768.f) - mu2 * mu2;
    float rstd2 = rsqrtf(var2 + 1e-5f);
    #pragma unroll
    for (int i = 0; i < 3; i++) {
        int idx = tid + 256 * i;
        g_h[(long long)row * D_MODEL + idx] = (w[i] - mu2) * rstd2 * ga[idx] + ba[idx];
    }
}

__global__ void ln_kernel(const float* __restrict__ src, float* __restrict__ dst,
                          const float* __restrict__ g, const float* __restrict__ b) {
    __shared__ float s1[256], s2[256];
    int row = blockIdx.x;
    int tid = threadIdx.x;
    const float* p = src + (long long)row * D_MODEL;
    float v[3]; float sum = 0.f, sq = 0.f;
    #pragma unroll
    for (int i = 0; i < 3; i++) {
        v[i] = p[tid + 256 * i];
        sum += v[i]; sq += v[i] * v[i];
    }
    block_reduce2(sum, sq, s1, s2);
    float mu = sum * (1.f / 768.f);
    float var = sq * (1.f / 768.f) - mu * mu;
    float rstd = rsqrtf(var + 1e-5f);
    #pragma unroll
    for (int i = 0; i < 3; i++) {
        int idx = tid + 256 * i;
        dst[(long long)row * D_MODEL + idx] = (v[i] - mu) * rstd * g[idx] + b[idx];
    }
}

// ---------------- softmax ----------------
// row r attends keys [0, kmax), kmax = r<784 ? 1568 : (r/196+1)*196.
// Zeroes [kmax, zend) where zend matches the PV kernel's K bound for the
// 128-row tile containing r.
__global__ void softmax_kernel() {
    __shared__ float sb[256];
    __shared__ float vals[L_TOT];
    int r = blockIdx.x;
    int z = blockIdx.y;
    float* p = g_dots + (long long)z * L_TOT * L_TOT + (long long)r * L_TOT;
    int kmax = (r < T_LEN) ? L_TOT : ((r / NPATCH) + 1) * NPATCH;
    int m0t = r & ~127;
    int ktile = (m0t < T_LEN) ? L_TOT
                              : ((min(m0t + 127, L_TOT - 1) / NPATCH) + 1) * NPATCH;
    int zend = (ktile + 15) & ~15;
    int tid = threadIdx.x;

    float m = -1e30f;
    for (int j = tid; j < kmax; j += 256) m = fmaxf(m, p[j]);
    sb[tid] = m; __syncthreads();
    #pragma unroll
    for (int s = 128; s; s >>= 1) {
        if (tid < s) sb[tid] = fmaxf(sb[tid], sb[tid + s]);
        __syncthreads();
    }
    m = sb[0]; __syncthreads();

    float sum = 0.f;
    for (int j = tid; j < kmax; j += 256) {
        float e = expf(p[j] - m);
        vals[j] = e;
        sum += e;
    }
    sb[tid] = sum; __syncthreads();
    #pragma unroll
    for (int s = 128; s; s >>= 1) {
        if (tid < s) sb[tid] += sb[tid + s];
        __syncthreads();
    }
    float inv = 1.f / sb[0];
    __syncthreads();

    for (int j = tid; j < kmax; j += 256) p[j] = vals[j] * inv;
    for (int j = kmax + tid; j < zend; j += 256) p[j] = 0.f;
}

__global__ void extract_kernel(float* __restrict__ out) {
    long long i = (long long)blockIdx.x * 256 + threadIdx.x;
    const long long TOT = (long long)BATCH * T_LEN * D_MODEL;
    if (i >= TOT) return;
    long long d = i % D_MODEL;
    long long t = (i / D_MODEL) % T_LEN;
    long long b = i / ((long long)D_MODEL * T_LEN);
    out[i] = g_xaug[((long long)b * L_TOT + T_LEN + t) * D_MODEL + d];
}

// ---------------- launch ----------------
extern "C" void kernel_launch(void* const* d_in, const int* in_sizes, int n_in,
                              void* d_out, int out_size) {
    const float* x        = (const float*)d_in[0];
    const float* memory   = (const float*)d_in[1];
    const float* ln_att_g = (const float*)d_in[2];
    const float* ln_att_b = (const float*)d_in[3];
    const float* w_qkv    = (const float*)d_in[4];
    const float* w_out    = (const float*)d_in[5];
    const float* b_out    = (const float*)d_in[6];
    const float* ln1_g    = (const float*)d_in[7];
    const float* ln1_b    = (const float*)d_in[8];
    const float* ln2_g    = (const float*)d_in[9];
    const float* ln2_b    = (const float*)d_in[10];
    const float* w1       = (const float*)d_in[11];
    const float* b1       = (const float*)d_in[12];
    const float* w2       = (const float*)d_in[13];
    const float* b2       = (const float*)d_in[14];
    float* out = (float*)d_out;

    float *xaug, *h, *qkv, *dots, *ctx, *y2, *ff;
    cudaGetSymbolAddress((void**)&xaug, g_xaug);
    cudaGetSymbolAddress((void**)&h,    g_h);
    cudaGetSymbolAddress((void**)&qkv,  g_qkv);
    cudaGetSymbolAddress((void**)&dots, g_dots);
    cudaGetSymbolAddress((void**)&ctx,  g_ctx);
    cudaGetSymbolAddress((void**)&y2,   g_y2);
    cudaGetSymbolAddress((void**)&ff,   g_ff);

    // 1) x_aug = ln1(concat(mem, x)); h = ln_att(x_aug)
    ln_build_kernel<<<ROWS, 256>>>(x, memory, ln1_g, ln1_b, ln_att_g, ln_att_b);

    // 2) qkv = h @ w_qkv^T   [6272, 2304]
    mma_gemm<128, true, false, false, false><<<dim3(18, 49, 1), 256>>>(
        h, w_qkv, qkv, nullptr, nullptr,
        ROWS, 3 * D_MODEL, D_MODEL, D_MODEL, D_MODEL, 3 * D_MODEL,
        0, 0, 0, 0, 0, 0, 1, 1.f, 0, 0);

    // 3) dots = Q @ K^T * scale (skip fully masked tiles)
    mma_gemm<128, true, false, false, false><<<dim3(13, 13, 48), 256>>>(
        qkv, qkv + D_MODEL, dots, nullptr, nullptr,
        L_TOT, L_TOT, DIM_HEAD, 3 * D_MODEL, 3 * D_MODEL, L_TOT,
        (long long)L_TOT * 3 * D_MODEL, DIM_HEAD,
        (long long)L_TOT * 3 * D_MODEL, DIM_HEAD,
        (long long)N_HEADS * L_TOT * L_TOT, (long long)L_TOT * L_TOT,
        N_HEADS, 0.125f, 1, 0);

    // 4) masked softmax
    softmax_kernel<<<dim3(L_TOT, 48), 256>>>();

    // 5) ctx = P @ V (K-loop bounded by tile kmax)
    mma_gemm<64, false, false, false, false><<<dim3(1, 13, 48), 256>>>(
        dots, qkv + 2 * D_MODEL, ctx, nullptr, nullptr,
        L_TOT, DIM_HEAD, L_TOT, L_TOT, 3 * D_MODEL, D_MODEL,
        (long long)N_HEADS * L_TOT * L_TOT, (long long)L_TOT * L_TOT,
        (long long)L_TOT * 3 * D_MODEL, DIM_HEAD,
        (long long)L_TOT * D_MODEL, DIM_HEAD,
        N_HEADS, 1.f, 0, 1);

    // 6) xaug += ctx @ w_out^T + b_out
    mma_gemm<128, true, true, true, false><<<dim3(6, 49, 1), 256>>>(
        ctx, w_out, xaug, b_out, xaug,
        ROWS, D_MODEL, D_MODEL, D_MODEL, D_MODEL, D_MODEL,
        0, 0, 0, 0, 0, 0, 1, 1.f, 0, 0);

    // 7) y2 = ln2(xaug)
    ln_kernel<<<ROWS, 256>>>(xaug, y2, ln2_g, ln2_b);

    // 8) ff = silu(y2 @ w1^T + b1)
    mma_gemm<128, true, true, false, true><<<dim3(24, 49, 1), 256>>>(
        y2, w1, ff, b1, nullptr,
        ROWS, D_FF, D_MODEL, D_MODEL, D_MODEL, D_FF,
        0, 0, 0, 0, 0, 0, 1, 1.f, 0, 0);

    // 9) xaug += ff @ w2^T + b2
    mma_gemm<128, true, true, true, false><<<dim3(6, 49, 1), 256>>>(
        ff, w2, xaug, b2, xaug,
        ROWS, D_MODEL, D_FF, D_FF, D_FF, D_MODEL,
        0, 0, 0, 0, 0, 0, 1, 1.f, 0, 0);

    // 10) extract last T rows
    long long tot = (long long)BATCH * T_LEN * D_MODEL;
    extract_kernel<<<(unsigned)((tot + 255) / 256), 256>>>(out);
}

// round 3
// speedup vs baseline: 3.6282x; 1.3828x over previous
#include <cuda_runtime.h>
#include <math.h>

#define L_TOT 1568
#define T_LEN 784
#define D_MODEL 768
#define N_HEADS 12
#define DIM_HEAD 64
#define D_FF 3072
#define BATCH 4
#define ROWS (BATCH * L_TOT)          // 6272
#define NPATCH 196

// ---------------- scratch ----------------
__device__ float g_xaug[ROWS * D_MODEL];
__device__ float g_h[ROWS * D_MODEL];
__device__ float g_qkv[ROWS * 3 * D_MODEL];
__device__ float g_ctx[ROWS * D_MODEL];
__device__ float g_y2[ROWS * D_MODEL];
__device__ float g_ff[ROWS * D_FF];

// ---------------- small helpers ----------------
__device__ __forceinline__ unsigned smem_u32(const void* p) {
    unsigned r;
    asm("{ .reg .u64 t; cvta.to.shared.u64 t, %1; cvt.u32.u64 %0, t; }" : "=r"(r) : "l"(p));
    return r;
}
__device__ __forceinline__ void cp16(unsigned dst, const void* src, bool valid) {
    int sz = valid ? 16 : 0;
    asm volatile("cp.async.cg.shared.global [%0], [%1], 16, %2;" :: "r"(dst), "l"(src), "r"(sz));
}
__device__ __forceinline__ unsigned f2tf(float f) {
    unsigned u;
    asm("cvt.rna.tf32.f32 %0, %1;" : "=r"(u) : "f"(f));
    return u;
}
__device__ __forceinline__ void mma_tf32(float4& d, const unsigned a[4], const unsigned b[2]) {
    asm volatile(
        "mma.sync.aligned.m16n8k8.row.col.f32.tf32.tf32.f32 "
        "{%0,%1,%2,%3}, {%4,%5,%6,%7}, {%8,%9}, {%0,%1,%2,%3};"
        : "+f"(d.x), "+f"(d.y), "+f"(d.z), "+f"(d.w)
        : "r"(a[0]), "r"(a[1]), "r"(a[2]), "r"(a[3]), "r"(b[0]), "r"(b[1]));
}

// ---------------- tf32 tensor-core GEMM (dense projections) ----------------
// C[m,n] = scale * sum_k A[m,k] * B[n,k]   (B row-major [N,K])
// Epilogue: +bias[n]; silu; +res.
template <bool BIAS, bool RES, bool SILU>
__global__ void __launch_bounds__(256, 1)
mma_gemm(const float* __restrict__ A, const float* __restrict__ B,
         float* __restrict__ C, const float* __restrict__ bias, const float* __restrict__ res,
         int M, int N, int K, int lda, int ldb, int ldc, float scale) {
    const int BM = 128, BN = 128, BK = 16, PAD = 20;
    const int NT = 8;

    __shared__ float As[2][BM * PAD];
    __shared__ float Bs[2][BN * PAD];

    int tid = threadIdx.x;
    int m0 = blockIdx.y * BM, n0 = blockIdx.x * BN;
    int warp = tid >> 5, lane = tid & 31;
    int wm = warp & 3, wn = warp >> 2;
    int mw = m0 + wm * 32;
    int nw = n0 + wn * 64;
    int g = lane >> 2, tg = lane & 3;

    float4 acc[2][NT];
    #pragma unroll
    for (int i = 0; i < 2; i++)
        #pragma unroll
        for (int j = 0; j < NT; j++) acc[i][j] = make_float4(0.f, 0.f, 0.f, 0.f);

    unsigned sA = smem_u32(As), sB = smem_u32(Bs);

    auto load_stage = [&](int ks, int buf) {
        #pragma unroll
        for (int i = 0; i < 2; i++) {
            int c = tid + i * 256;
            int m = c >> 2, kc = (c & 3) << 2;
            unsigned dst = sA + (buf * BM * PAD + m * PAD + kc) * 4;
            cp16(dst, A + (long long)(m0 + m) * lda + ks + kc, (m0 + m) < M);
        }
        #pragma unroll
        for (int i = 0; i < 2; i++) {
            int c = tid + i * 256;
            int n = c >> 2, kc = (c & 3) << 2;
            unsigned dst = sB + (buf * BN * PAD + n * PAD + kc) * 4;
            cp16(dst, B + (long long)(n0 + n) * ldb + ks + kc, (n0 + n) < N);
        }
    };

    auto compute = [&](int buf) {
        const float* Ap = &As[0][buf * BM * PAD];
        const float* Bp = &Bs[0][buf * BN * PAD];
        #pragma unroll
        for (int ks = 0; ks < BK; ks += 8) {
            unsigned af[2][4];
            #pragma unroll
            for (int i = 0; i < 2; i++) {
                const float* p = Ap + (wm * 32 + i * 16 + g) * PAD + ks + tg;
                af[i][0] = f2tf(p[0]);
                af[i][1] = f2tf(p[8 * PAD]);
                af[i][2] = f2tf(p[4]);
                af[i][3] = f2tf(p[8 * PAD + 4]);
            }
            unsigned bf[NT][2];
            #pragma unroll
            for (int j = 0; j < NT; j++) {
                const float* p = Bp + (wn * 64 + j * 8 + g) * PAD + ks + tg;
                bf[j][0] = f2tf(p[0]);
                bf[j][1] = f2tf(p[4]);
            }
            #pragma unroll
            for (int i = 0; i < 2; i++)
                #pragma unroll
                for (int j = 0; j < NT; j++)
                    mma_tf32(acc[i][j], af[i], bf[j]);
        }
    };

    int numK = K / BK;
    load_stage(0, 0);
    asm volatile("cp.async.commit_group;");
    for (int it = 0; it < numK; it++) {
        if (it + 1 < numK) {
            load_stage((it + 1) * BK, (it + 1) & 1);
            asm volatile("cp.async.commit_group;");
            asm volatile("cp.async.wait_group 1;");
        } else {
            asm volatile("cp.async.wait_group 0;");
        }
        __syncthreads();
        compute(it & 1);
        __syncthreads();
    }

    #pragma unroll
    for (int i = 0; i < 2; i++) {
        #pragma unroll
        for (int half = 0; half < 2; half++) {
            int r = mw + i * 16 + g + half * 8;
            if (r >= M) continue;
            long long base = (long long)r * ldc;
            #pragma unroll
            for (int j = 0; j < NT; j++) {
                float v0 = half ? acc[i][j].z : acc[i][j].x;
                float v1 = half ? acc[i][j].w : acc[i][j].y;
                int c0 = nw + j * 8 + tg * 2;
                if (c0 < N) {
                    float v = v0 * scale;
                    if (BIAS) v += bias[c0];
                    if (SILU) v = v / (1.f + expf(-v));
                    if (RES) v += res[base + c0];
                    C[base + c0] = v;
                }
                if (c0 + 1 < N) {
                    float v = v1 * scale;
                    if (BIAS) v += bias[c0 + 1];
                    if (SILU) v = v / (1.f + expf(-v));
                    if (RES) v += res[base + c0 + 1];
                    C[base + c0 + 1] = v;
                }
            }
        }
    }
}

// ---------------- fused flash attention ----------------
// Grid: (13 q-tiles, 48 b*h). Block 256 (8 warps), each warp owns 16 full rows.
// qkv layout per row: [q(768) | k(768) | v(768)], head h occupies cols h*64..h*64+63.
#define PADQ 68
__global__ void __launch_bounds__(256, 1)
flash_attn(const float* __restrict__ qkv, float* __restrict__ ctx) {
    extern __shared__ float sm[];
    float* sP = sm;                        // 128 * PADQ
    float* sK = sm + 128 * PADQ;           // 2 * 64 * PADQ
    float* sV = sK + 2 * 64 * PADQ;        // 2 * 64 * PADQ

    int tid = threadIdx.x;
    int warp = tid >> 5, lane = tid & 31;
    int g = lane >> 2, tg = lane & 3;
    int bh = blockIdx.y;
    int b = bh / N_HEADS, h = bh - b * N_HEADS;
    int m0 = blockIdx.x * 128;

    const float* base = qkv + (long long)b * L_TOT * (3 * D_MODEL);
    const float* Qp = base + h * 64;
    const float* Kp = base + D_MODEL + h * 64;
    const float* Vp = base + 2 * D_MODEL + h * 64;

    // stage Q tile (128x64) into sP
    #pragma unroll
    for (int i = 0; i < 8; i++) {
        int c = tid + i * 256;
        int m = c >> 4, dc = (c & 15) << 2;
        unsigned dst = smem_u32(sP + m * PADQ + dc);
        cp16(dst, Qp + (long long)(m0 + m) * (3 * D_MODEL) + dc, (m0 + m) < L_TOT);
    }
    asm volatile("cp.async.commit_group;");
    asm volatile("cp.async.wait_group 0;");
    __syncthreads();

    unsigned qf[8][4];
    {
        const float* qp = sP + (warp * 16) * PADQ;
        #pragma unroll
        for (int ks = 0; ks < 8; ks++) {
            qf[ks][0] = f2tf(qp[g * PADQ + 8 * ks + tg]);
            qf[ks][1] = f2tf(qp[(g + 8) * PADQ + 8 * ks + tg]);
            qf[ks][2] = f2tf(qp[g * PADQ + 8 * ks + tg + 4]);
            qf[ks][3] = f2tf(qp[(g + 8) * PADQ + 8 * ks + tg + 4]);
        }
    }
    __syncthreads();   // everyone done reading Q before sP is reused for P

    int r0 = m0 + warp * 16 + g;
    int r1 = r0 + 8;
    int km0 = (r0 < T_LEN) ? L_TOT : ((r0 / NPATCH) + 1) * NPATCH;
    int km1 = (r1 < T_LEN) ? L_TOT : ((r1 / NPATCH) + 1) * NPATCH;

    float mrow0 = -1e30f, mrow1 = -1e30f, lrow0 = 0.f, lrow1 = 0.f;
    float4 accO[8];
    #pragma unroll
    for (int j = 0; j < 8; j++) accO[j] = make_float4(0.f, 0.f, 0.f, 0.f);

    int rlast = min(m0 + 127, L_TOT - 1);
    int kend = (m0 < T_LEN) ? L_TOT : ((rlast / NPATCH) + 1) * NPATCH;
    int ntiles = (kend + 63) >> 6;

    auto loadKV = [&](int t, int buf) {
        int n0t = t * 64;
        #pragma unroll
        for (int i = 0; i < 4; i++) {
            int c = tid + i * 256;
            int kv = c >> 4, dc = (c & 15) << 2;
            bool ok = (n0t + kv) < L_TOT;
            long long goff = (long long)(n0t + kv) * (3 * D_MODEL) + dc;
            cp16(smem_u32(sK + buf * 64 * PADQ + kv * PADQ + dc), Kp + goff, ok);
            cp16(smem_u32(sV + buf * 64 * PADQ + kv * PADQ + dc), Vp + goff, ok);
        }
    };

    loadKV(0, 0);
    asm volatile("cp.async.commit_group;");

    float* pp = sP + (warp * 16) * PADQ;

    for (int t = 0; t < ntiles; t++) {
        int buf = t & 1;
        if (t + 1 < ntiles) {
            loadKV(t + 1, buf ^ 1);
            asm volatile("cp.async.commit_group;");
            asm volatile("cp.async.wait_group 1;");
        } else {
            asm volatile("cp.async.wait_group 0;");
        }
        __syncthreads();

        // S = Q @ K^T for this 64-col tile
        float4 s[8];
        #pragma unroll
        for (int j = 0; j < 8; j++) s[j] = make_float4(0.f, 0.f, 0.f, 0.f);
        const float* kb = sK + buf * 64 * PADQ;
        #pragma unroll
        for (int j = 0; j < 8; j++) {
            const float* kr = kb + (8 * j + g) * PADQ;
            #pragma unroll
            for (int ks = 0; ks < 8; ks++) {
                unsigned bf[2];
                bf[0] = f2tf(kr[8 * ks + tg]);
                bf[1] = f2tf(kr[8 * ks + tg + 4]);
                mma_tf32(s[j], qf[ks], bf);
            }
        }

        // scale + mask + online softmax
        float tmax0 = -1e30f, tmax1 = -1e30f;
        #pragma unroll
        for (int j = 0; j < 8; j++) {
            int c0 = t * 64 + 8 * j + 2 * tg;
            int c1 = c0 + 1;
            s[j].x = (c0 < km0) ? s[j].x * 0.125f : -1e30f;
            s[j].y = (c1 < km0) ? s[j].y * 0.125f : -1e30f;
            s[j].z = (c0 < km1) ? s[j].z * 0.125f : -1e30f;
            s[j].w = (c1 < km1) ? s[j].w * 0.125f : -1e30f;
            tmax0 = fmaxf(tmax0, fmaxf(s[j].x, s[j].y));
            tmax1 = fmaxf(tmax1, fmaxf(s[j].z, s[j].w));
        }
        tmax0 = fmaxf(tmax0, __shfl_xor_sync(0xffffffffu, tmax0, 1));
        tmax0 = fmaxf(tmax0, __shfl_xor_sync(0xffffffffu, tmax0, 2));
        tmax1 = fmaxf(tmax1, __shfl_xor_sync(0xffffffffu, tmax1, 1));
        tmax1 = fmaxf(tmax1, __shfl_xor_sync(0xffffffffu, tmax1, 2));

        float mn0 = fmaxf(mrow0, tmax0), mn1 = fmaxf(mrow1, tmax1);
        float al0 = __expf(mrow0 - mn0), al1 = __expf(mrow1 - mn1);
        mrow0 = mn0; mrow1 = mn1;

        float rs0 = 0.f, rs1 = 0.f;
        #pragma unroll
        for (int j = 0; j < 8; j++) {
            s[j].x = __expf(s[j].x - mn0);
            s[j].y = __expf(s[j].y - mn0);
            s[j].z = __expf(s[j].z - mn1);
            s[j].w = __expf(s[j].w - mn1);
            rs0 += s[j].x + s[j].y;
            rs1 += s[j].z + s[j].w;
            *(float2*)&pp[g * PADQ + 8 * j + 2 * tg] = make_float2(s[j].x, s[j].y);
            *(float2*)&pp[(g + 8) * PADQ + 8 * j + 2 * tg] = make_float2(s[j].z, s[j].w);
        }
        rs0 += __shfl_xor_sync(0xffffffffu, rs0, 1);
        rs0 += __shfl_xor_sync(0xffffffffu, rs0, 2);
        rs1 += __shfl_xor_sync(0xffffffffu, rs1, 1);
        rs1 += __shfl_xor_sync(0xffffffffu, rs1, 2);
        lrow0 = lrow0 * al0 + rs0;
        lrow1 = lrow1 * al1 + rs1;

        #pragma unroll
        for (int j = 0; j < 8; j++) {
            accO[j].x *= al0; accO[j].y *= al0;
            accO[j].z *= al1; accO[j].w *= al1;
        }
        __syncwarp();

        // O += P @ V   (V in smem as [kv][d], read transposed)
        const float* vb = sV + buf * 64 * PADQ;
        #pragma unroll
        for (int ks = 0; ks < 8; ks++) {
            unsigned af[4];
            af[0] = f2tf(pp[g * PADQ + 8 * ks + tg]);
            af[1] = f2tf(pp[(g + 8) * PADQ + 8 * ks + tg]);
            af[2] = f2tf(pp[g * PADQ + 8 * ks + tg + 4]);
            af[3] = f2tf(pp[(g + 8) * PADQ + 8 * ks + tg + 4]);
            const float* v0 = vb + (8 * ks + tg) * PADQ;
            const float* v1 = vb + (8 * ks + tg + 4) * PADQ;
            #pragma unroll
            for (int j = 0; j < 8; j++) {
                unsigned bf[2];
                bf[0] = f2tf(v0[8 * j + g]);
                bf[1] = f2tf(v1[8 * j + g]);
                mma_tf32(accO[j], af, bf);
            }
        }
        __syncthreads();
    }

    float inv0 = 1.f / lrow0, inv1 = 1.f / lrow1;
    if (r0 < L_TOT) {
        float* op = ctx + ((long long)b * L_TOT + r0) * D_MODEL + h * 64;
        #pragma unroll
        for (int j = 0; j < 8; j++)
            *(float2*)&op[8 * j + 2 * tg] = make_float2(accO[j].x * inv0, accO[j].y * inv0);
    }
    if (r1 < L_TOT) {
        float* op = ctx + ((long long)b * L_TOT + r1) * D_MODEL + h * 64;
        #pragma unroll
        for (int j = 0; j < 8; j++)
            *(float2*)&op[8 * j + 2 * tg] = make_float2(accO[j].z * inv1, accO[j].w * inv1);
    }
}

// ---------------- layernorms ----------------
__device__ __forceinline__ void block_reduce2(float& a, float& b, float* s1, float* s2) {
    int tid = threadIdx.x;
    s1[tid] = a; s2[tid] = b; __syncthreads();
    #pragma unroll
    for (int s = 128; s; s >>= 1) {
        if (tid < s) { s1[tid] += s1[tid + s]; s2[tid] += s2[tid + s]; }
        __syncthreads();
    }
    a = s1[0]; b = s2[0]; __syncthreads();
}

__global__ void ln_build_kernel(const float* __restrict__ x,
                                const float* __restrict__ mem,
                                const float* __restrict__ g1, const float* __restrict__ b1,
                                const float* __restrict__ ga, const float* __restrict__ ba) {
    __shared__ float s1[256], s2[256];
    int row = blockIdx.x;
    int b = row / L_TOT;
    int l = row - b * L_TOT;
    const float* src = (l < T_LEN)
        ? mem + ((long long)b * 1024 + l) * D_MODEL
        : x   + ((long long)b * T_LEN + (l - T_LEN)) * D_MODEL;
    int tid = threadIdx.x;
    float v[3]; float sum = 0.f, sq = 0.f;
    #pragma unroll
    for (int i = 0; i < 3; i++) {
        v[i] = src[tid + 256 * i];
        sum += v[i]; sq += v[i] * v[i];
    }
    block_reduce2(sum, sq, s1, s2);
    float mu = sum * (1.f / 768.f);
    float var = sq * (1.f / 768.f) - mu * mu;
    float rstd = rsqrtf(var + 1e-5f);

    float w[3]; sum = 0.f; sq = 0.f;
    #pragma unroll
    for (int i = 0; i < 3; i++) {
        int idx = tid + 256 * i;
        w[i] = (v[i] - mu) * rstd * g1[idx] + b1[idx];
        g_xaug[(long long)row * D_MODEL + idx] = w[i];
        sum += w[i]; sq += w[i] * w[i];
    }
    block_reduce2(sum, sq, s1, s2);
    float mu2 = sum * (1.f / 768.f);
    float var2 = sq * (1.f / 768.f) - mu2 * mu2;
    float rstd2 = rsqrtf(var2 + 1e-5f);
    #pragma unroll
    for (int i = 0; i < 3; i++) {
        int idx = tid + 256 * i;
        g_h[(long long)row * D_MODEL + idx] = (w[i] - mu2) * rstd2 * ga[idx] + ba[idx];
    }
}

__global__ void ln_kernel(const float* __restrict__ src, float* __restrict__ dst,
                          const float* __restrict__ g, const float* __restrict__ b) {
    __shared__ float s1[256], s2[256];
    int row = blockIdx.x;
    int tid = threadIdx.x;
    const float* p = src + (long long)row * D_MODEL;
    float v[3]; float sum = 0.f, sq = 0.f;
    #pragma unroll
    for (int i = 0; i < 3; i++) {
        v[i] = p[tid + 256 * i];
        sum += v[i]; sq += v[i] * v[i];
    }
    block_reduce2(sum, sq, s1, s2);
    float mu = sum * (1.f / 768.f);
    float var = sq * (1.f / 768.f) - mu * mu;
    float rstd = rsqrtf(var + 1e-5f);
    #pragma unroll
    for (int i = 0; i < 3; i++) {
        int idx = tid + 256 * i;
        dst[(long long)row * D_MODEL + idx] = (v[i] - mu) * rstd * g[idx] + b[idx];
    }
}

__global__ void extract_kernel(float* __restrict__ out) {
    long long i = (long long)blockIdx.x * 256 + threadIdx.x;
    const long long TOT = (long long)BATCH * T_LEN * D_MODEL;
    if (i >= TOT) return;
    long long d = i % D_MODEL;
    long long t = (i / D_MODEL) % T_LEN;
    long long b = i / ((long long)D_MODEL * T_LEN);
    out[i] = g_xaug[((long long)b * L_TOT + T_LEN + t) * D_MODEL + d];
}

// ---------------- launch ----------------
extern "C" void kernel_launch(void* const* d_in, const int* in_sizes, int n_in,
                              void* d_out, int out_size) {
    const float* x        = (const float*)d_in[0];
    const float* memory   = (const float*)d_in[1];
    const float* ln_att_g = (const float*)d_in[2];
    const float* ln_att_b = (const float*)d_in[3];
    const float* w_qkv    = (const float*)d_in[4];
    const float* w_out    = (const float*)d_in[5];
    const float* b_out    = (const float*)d_in[6];
    const float* ln1_g    = (const float*)d_in[7];
    const float* ln1_b    = (const float*)d_in[8];
    const float* ln2_g    = (const float*)d_in[9];
    const float* ln2_b    = (const float*)d_in[10];
    const float* w1       = (const float*)d_in[11];
    const float* b1       = (const float*)d_in[12];
    const float* w2       = (const float*)d_in[13];
    const float* b2       = (const float*)d_in[14];
    float* out = (float*)d_out;

    float *xaug, *h, *qkv, *ctx, *y2, *ff;
    cudaGetSymbolAddress((void**)&xaug, g_xaug);
    cudaGetSymbolAddress((void**)&h,    g_h);
    cudaGetSymbolAddress((void**)&qkv,  g_qkv);
    cudaGetSymbolAddress((void**)&ctx,  g_ctx);
    cudaGetSymbolAddress((void**)&y2,   g_y2);
    cudaGetSymbolAddress((void**)&ff,   g_ff);

    const int FLASH_SMEM = (128 * PADQ + 4 * 64 * PADQ) * 4;  // 104448 B
    cudaFuncSetAttribute(flash_attn, cudaFuncAttributeMaxDynamicSharedMemorySize, FLASH_SMEM);

    // 1) x_aug = ln1(concat(mem, x)); h = ln_att(x_aug)
    ln_build_kernel<<<ROWS, 256>>>(x, memory, ln1_g, ln1_b, ln_att_g, ln_att_b);

    // 2) qkv = h @ w_qkv^T
    mma_gemm<false, false, false><<<dim3(18, 49), 256>>>(
        h, w_qkv, qkv, nullptr, nullptr,
        ROWS, 3 * D_MODEL, D_MODEL, D_MODEL, D_MODEL, 3 * D_MODEL, 1.f);

    // 3-5) fused attention -> ctx
    flash_attn<<<dim3(13, 48), 256, FLASH_SMEM>>>(qkv, ctx);

    // 6) xaug += ctx @ w_out^T + b_out
    mma_gemm<true, true, false><<<dim3(6, 49), 256>>>(
        ctx, w_out, xaug, b_out, xaug,
        ROWS, D_MODEL, D_MODEL, D_MODEL, D_MODEL, D_MODEL, 1.f);

    // 7) y2 = ln2(xaug)
    ln_kernel<<<ROWS, 256>>>(xaug, y2, ln2_g, ln2_b);

    // 8) ff = silu(y2 @ w1^T + b1)
    mma_gemm<true, false, true><<<dim3(24, 49), 256>>>(
        y2, w1, ff, b1, nullptr,
        ROWS, D_FF, D_MODEL, D_MODEL, D_MODEL, D_FF, 1.f);

    // 9) xaug += ff @ w2^T + b2
    mma_gemm<true, true, false><<<dim3(6, 49), 256>>>(
        ff, w2, xaug, b2, xaug,
        ROWS, D_MODEL, D_FF, D_FF, D_FF, D_MODEL, 1.f);

    // 10) extract last T rows
    long long tot = (long long)BATCH * T_LEN * D_MODEL;
    extract_kernel<<<(unsigned)((tot + 255) / 256), 256>>>(out);
}